// round 16
// baseline (speedup 1.0000x reference)
#include <cuda_runtime.h>
#include <cuda_bf16.h>
#include <cstdint>
#include <cstddef>

#define BB 256
#define TT 2048
#define II 64
#define HH 256
#define OO 64
#define FF 16
#define NB 2   // batches per CTA in the recurrence kernel (128 CTAs cover B=256)

typedef unsigned long long ull;

// ---- packed f32x2 helpers (exact fp32; FFMA2 is dual-throughput on sm_103a)
__device__ __forceinline__ ull pk2(float x, float y) {
    ull r; asm("mov.b64 %0, {%1, %2};" : "=l"(r) : "f"(x), "f"(y)); return r;
}
__device__ __forceinline__ void f2fma(ull& d, ull a, ull b) {
    asm("fma.rn.f32x2 %0, %1, %2, %0;" : "+l"(d) : "l"(a), "l"(b));
}
__device__ __forceinline__ float2 up2(ull v) {
    float2 f; asm("mov.b64 {%0, %1}, %2;" : "=f"(f.x), "=f"(f.y) : "l"(v)); return f;
}

// 512 MB scratch, reused in place: pre0 -> ys0 -> pre1 -> ys1. Layout [t][b][h].
__device__ float g_buf[(size_t)TT * BB * HH];

#define ASTR 68    // As row stride: 16B-aligned, low conflict
#define BSTR 260   // Bs row stride: 16B-aligned pair loads

// ---------------------------------------------------------------------------
// K1: pre0[t,b,n] = x[b,t,:] . W_ih0[n,:] + b_ih0[n] + b_hh0[n]
// ---------------------------------------------------------------------------
__global__ void __launch_bounds__(256)
pre0_kernel(const float* __restrict__ x, const float* __restrict__ Wih,
            const float* __restrict__ bih, const float* __restrict__ bhh) {
    extern __shared__ float sm[];
    float* As = sm;                 // [64 k][ASTR]
    float* Bs = sm + 64 * ASTR;     // [64 k][BSTR]
    const int tid = threadIdx.x;
    const int m0 = blockIdx.x * 64;

    for (int e = tid; e < 64 * 64; e += 256) {
        int r = e >> 6, k = e & 63;
        int m = m0 + r;
        int b = m & (BB - 1);
        int t = m >> 8;
        As[k * ASTR + r] = x[((size_t)b * TT + t) * II + k];
    }
    for (int e = tid; e < 64 * 256; e += 256) {
        int n = e >> 6, k = e & 63;
        Bs[k * BSTR + n] = Wih[n * II + k];
    }
    __syncthreads();

    const int tm = tid & 7;
    const int tn = tid >> 3;
    ull acc2[8][4];
#pragma unroll
    for (int i = 0; i < 8; i++)
#pragma unroll
        for (int j = 0; j < 4; j++) acc2[i][j] = 0ull;

#pragma unroll 8
    for (int k = 0; k < 64; k++) {
        const float4* ar = (const float4*)&As[k * ASTR + tm * 8];
        float4 a0 = ar[0], a1 = ar[1];
        const ulonglong2* br = (const ulonglong2*)&Bs[k * BSTR + tn * 8];
        ulonglong2 q0 = br[0], q1 = br[1];
        ull b2[4] = {q0.x, q0.y, q1.x, q1.y};
        float a[8] = {a0.x, a0.y, a0.z, a0.w, a1.x, a1.y, a1.z, a1.w};
#pragma unroll
        for (int i = 0; i < 8; i++) {
            ull ad = pk2(a[i], a[i]);
#pragma unroll
            for (int j = 0; j < 4; j++) f2fma(acc2[i][j], ad, b2[j]);
        }
    }

#pragma unroll
    for (int j = 0; j < 4; j++) {
        int n0 = tn * 8 + 2 * j;
        float bias0 = bih[n0] + bhh[n0];
        float bias1 = bih[n0 + 1] + bhh[n0 + 1];
#pragma unroll
        for (int i = 0; i < 8; i++) {
            float2 v = up2(acc2[i][j]);
            size_t row = (size_t)(m0 + tm * 8 + i) * HH;
            g_buf[row + n0]     = v.x + bias0;
            g_buf[row + n0 + 1] = v.y + bias1;
        }
    }
}

// ---------------------------------------------------------------------------
// K3: in-place pre1: buf[m,n] = buf[m,:] . W_ih1[n,:] + b_ih1[n] + b_hh1[n]
// ---------------------------------------------------------------------------
__global__ void __launch_bounds__(256, 2)
pre1_kernel(const float* __restrict__ Wih, const float* __restrict__ bih,
            const float* __restrict__ bhh) {
    extern __shared__ float sm[];
    float* As = sm;                    // [256 k][ASTR]
    float* Bs = sm + 256 * ASTR;       // [32 k][BSTR]
    const int tid = threadIdx.x;
    const int m0 = blockIdx.x * 64;

    for (int e = tid; e < 64 * 256; e += 256) {
        int r = e >> 8, k = e & 255;
        As[k * ASTR + r] = g_buf[(size_t)(m0 + r) * HH + k];
    }

    const int tm = tid & 7;
    const int tn = tid >> 3;
    ull acc2[8][4];
#pragma unroll
    for (int i = 0; i < 8; i++)
#pragma unroll
        for (int j = 0; j < 4; j++) acc2[i][j] = 0ull;

    for (int kc = 0; kc < 8; kc++) {
        const int k0 = kc * 32;
        __syncthreads();
        for (int e = tid; e < 32 * 256; e += 256) {
            int n = e >> 5, kk = e & 31;
            Bs[kk * BSTR + n] = Wih[n * HH + k0 + kk];
        }
        __syncthreads();
#pragma unroll 8
        for (int kk = 0; kk < 32; kk++) {
            const float4* ar = (const float4*)&As[(k0 + kk) * ASTR + tm * 8];
            float4 a0 = ar[0], a1 = ar[1];
            const ulonglong2* br = (const ulonglong2*)&Bs[kk * BSTR + tn * 8];
            ulonglong2 q0 = br[0], q1 = br[1];
            ull b2[4] = {q0.x, q0.y, q1.x, q1.y};
            float a[8] = {a0.x, a0.y, a0.z, a0.w, a1.x, a1.y, a1.z, a1.w};
#pragma unroll
            for (int i = 0; i < 8; i++) {
                ull ad = pk2(a[i], a[i]);
#pragma unroll
                for (int j = 0; j < 4; j++) f2fma(acc2[i][j], ad, b2[j]);
            }
        }
    }

#pragma unroll
    for (int j = 0; j < 4; j++) {
        int n0 = tn * 8 + 2 * j;
        float bias0 = bih[n0] + bhh[n0];
        float bias1 = bih[n0 + 1] + bhh[n0 + 1];
#pragma unroll
        for (int i = 0; i < 8; i++) {
            float2 v = up2(acc2[i][j]);
            size_t row = (size_t)(m0 + tm * 8 + i) * HH;
            g_buf[row + n0]     = v.x + bias0;
            g_buf[row + n0 + 1] = v.y + bias1;
        }
    }
}

// ---------------------------------------------------------------------------
// K2: recurrence v5 — lane-interleaved k-split, shfl combine, 1 sync/step.
// 128 CTAs x 512 threads, NB=2 batches each. Thread (n = tid>>1, half = tid&1)
// computes k-range [half*128, half*128+128) of row n:
//   - k_local  0..79   from 40 ull register pairs (80 regs)
//   - k_local 80..127  from a 96 KB smem tile (12 LDS.128/step, per-lane)
// The two k-halves of row n sit in ADJACENT LANES, so the cross-half partial
// combine is one shfl_xor — no psum smem, no extra __syncthreads. Even lane
// finalizes tanh + stores. LDS floor drops 2048 -> ~1792 wf/SM/step.
// ---------------------------------------------------------------------------
__global__ void __launch_bounds__(512, 1)
rec_kernel(const float* __restrict__ Whh, const float* __restrict__ h0,
           float* __restrict__ hT) {
    extern __shared__ float smd[];
    // Wsm: ulonglong2[12][512] = 96 KB | hbuf [2][NB][256] = 4 KB
    ulonglong2* Wsm = (ulonglong2*)smd;
    float* hbuf = smd + 12 * 512 * 4;     // 24576 floats into smd

    const int tid = threadIdx.x;
    const int n = tid >> 1;
    const int half = tid & 1;
    const int b0 = blockIdx.x * NB;
    const int kb = half * 128;

    // Register W: k_local 0..79 as 40 ull pairs (pair j = floats 2j, 2j+1).
    ull W2[40];
    const ulonglong2* wp = (const ulonglong2*)(Whh + (size_t)n * HH + kb);
#pragma unroll
    for (int q = 0; q < 20; q++) {
        ulonglong2 v = wp[q];
        W2[2 * q]     = v.x;
        W2[2 * q + 1] = v.y;
    }
    // Smem W: k_local 80..127 (12 x ulonglong2 per thread, per-lane distinct).
#pragma unroll
    for (int j = 0; j < 12; j++)
        Wsm[j * 512 + tid] = wp[20 + j];

    // h init into buffer 0, layout [b][k]; 512 threads cover NB*256 exactly.
    {
        int b = tid >> 8, k = tid & 255;
        hbuf[b * 256 + k] = h0[(b0 + b) * HH + k];
    }
    __syncthreads();

    for (int t = 0; t < TT; t++) {
        const int p = t & 1;
        const float* cur = hbuf + p * NB * 256;
        float* nxt = hbuf + (p ^ 1) * NB * 256;

        // even lanes prefetch pre-activations (LDG hides under FMA block)
        float pr[NB];
        if (half == 0) {
#pragma unroll
            for (int b = 0; b < NB; b++)
                pr[b] = g_buf[((size_t)t * BB + b0 + b) * HH + n];
        }

        // 4 accumulator chains: (reg-part, smem-part) x NB
        ull accR[NB], accS[NB];
#pragma unroll
        for (int b = 0; b < NB; b++) { accR[b] = 0ull; accS[b] = 0ull; }

        // register part: k_local 0..79
#pragma unroll
        for (int q = 0; q < 20; q++) {
#pragma unroll
            for (int b = 0; b < NB; b++) {
                ulonglong2 hv = *(const ulonglong2*)&cur[b * 256 + kb + q * 4];
                f2fma(accR[b], hv.x, W2[2 * q]);
                f2fma(accR[b], hv.y, W2[2 * q + 1]);
            }
        }
        // smem part: k_local 80..127
#pragma unroll
        for (int j = 0; j < 12; j++) {
            ulonglong2 w = Wsm[j * 512 + tid];
#pragma unroll
            for (int b = 0; b < NB; b++) {
                ulonglong2 hv =
                    *(const ulonglong2*)&cur[b * 256 + kb + 80 + j * 4];
                f2fma(accS[b], hv.x, w.x);
                f2fma(accS[b], hv.y, w.y);
            }
        }

        // combine: horizontal add + cross-half shfl (adjacent lane)
#pragma unroll
        for (int b = 0; b < NB; b++) {
            float2 vr = up2(accR[b]);
            float2 vs = up2(accS[b]);
            float s = (vr.x + vr.y) + (vs.x + vs.y);
            float o = __shfl_xor_sync(0xFFFFFFFFu, s, 1);
            if (half == 0) {
                float hv = tanhf(pr[b] + s + o);
                nxt[b * 256 + n] = hv;
                g_buf[((size_t)t * BB + b0 + b) * HH + n] = hv;
            }
        }
        __syncthreads();   // nxt visible to all before it becomes cur
    }

    // TT even -> final state in buffer 0
    if (half == 0) {
#pragma unroll
        for (int b = 0; b < NB; b++)
            hT[(b0 + b) * HH + n] = hbuf[b * 256 + n];
    }
}

// ---------------------------------------------------------------------------
// K4: fc over the last F timesteps:
// out[b,f,o] = ys1[T-F+f, b, :] . fc_W[o,:] + fc_b[o]
// ---------------------------------------------------------------------------
__global__ void __launch_bounds__(256)
fc_kernel(const float* __restrict__ Wfc, const float* __restrict__ bfc,
          float* __restrict__ out) {
    __shared__ __align__(16) float xs[FF][HH];
    const int b = blockIdx.x;
    const int tid = threadIdx.x;
    for (int idx = tid; idx < FF * HH; idx += 256) {
        int f = idx >> 8, h = idx & 255;
        int t = TT - FF + f;
        xs[f][h] = g_buf[((size_t)t * BB + b) * HH + h];
    }
    __syncthreads();
    for (int fo = tid; fo < FF * OO; fo += 256) {
        int f = fo >> 6, o = fo & 63;
        float s = 0.f;
        const float4* wr = (const float4*)(Wfc + (size_t)o * HH);
        const float4* xr = (const float4*)&xs[f][0];
#pragma unroll
        for (int q = 0; q < 64; q++) {
            float4 w = wr[q], xv = xr[q];
            s += w.x * xv.x + w.y * xv.y + w.z * xv.z + w.w * xv.w;
        }
        out[((size_t)b * FF + f) * OO + o] = s + bfc[o];
    }
}

// ---------------------------------------------------------------------------
extern "C" void kernel_launch(void* const* d_in, const int* in_sizes, int n_in,
                              void* d_out, int out_size) {
    const float* x      = (const float*)d_in[0];
    const float* hidden = (const float*)d_in[1];
    const float* W_ih0  = (const float*)d_in[2];
    const float* W_hh0  = (const float*)d_in[3];
    const float* b_ih0  = (const float*)d_in[4];
    const float* b_hh0  = (const float*)d_in[5];
    const float* W_ih1  = (const float*)d_in[6];
    const float* W_hh1  = (const float*)d_in[7];
    const float* b_ih1  = (const float*)d_in[8];
    const float* b_hh1  = (const float*)d_in[9];
    const float* fc_W   = (const float*)d_in[10];
    const float* fc_b   = (const float*)d_in[11];

    float* out = (float*)d_out;                 // [B, F, O]
    float* hT  = out + (size_t)BB * FF * OO;    // [2, B, H]

    const int sm1 = (64 * ASTR + 64 * BSTR) * 4;            // ~84 KB
    const int sm3 = (256 * ASTR + 32 * BSTR) * 4;           // ~101 KB (occ 2)
    const int smr = 12 * 512 * 16 + 2 * NB * 256 * 4;       // 96 KB + 4 KB
    cudaFuncSetAttribute(pre0_kernel, cudaFuncAttributeMaxDynamicSharedMemorySize, sm1);
    cudaFuncSetAttribute(pre1_kernel, cudaFuncAttributeMaxDynamicSharedMemorySize, sm3);
    cudaFuncSetAttribute(rec_kernel,  cudaFuncAttributeMaxDynamicSharedMemorySize, smr);

    const int mblocks = TT * BB / 64;   // 8192
    const int rblocks = BB / NB;        // 128 CTAs, 512 threads each

    pre0_kernel<<<mblocks, 256, sm1>>>(x, W_ih0, b_ih0, b_hh0);
    rec_kernel<<<rblocks, 512, smr>>>(W_hh0, hidden, hT);
    pre1_kernel<<<mblocks, 256, sm3>>>(W_ih1, b_ih1, b_hh1);
    rec_kernel<<<rblocks, 512, smr>>>(W_hh1, hidden + (size_t)BB * HH,
                                      hT + (size_t)BB * HH);
    fc_kernel<<<BB, 256>>>(fc_W, fc_b, out);
}

// round 17
// speedup vs baseline: 1.3521x; 1.3521x over previous
#include <cuda_runtime.h>
#include <cuda_bf16.h>
#include <cstdint>
#include <cstddef>

#define BB 256
#define TT 2048
#define II 64
#define HH 256
#define OO 64
#define FF 16
#define NB 2   // batches per CTA in the recurrence kernel (128 CTAs cover B=256)

typedef unsigned long long ull;

// ---- packed f32x2 helpers (exact fp32; FFMA2 is dual-throughput on sm_103a)
__device__ __forceinline__ ull pk2(float x, float y) {
    ull r; asm("mov.b64 %0, {%1, %2};" : "=l"(r) : "f"(x), "f"(y)); return r;
}
__device__ __forceinline__ void f2fma(ull& d, ull a, ull b) {
    asm("fma.rn.f32x2 %0, %1, %2, %0;" : "+l"(d) : "l"(a), "l"(b));
}
__device__ __forceinline__ float2 up2(ull v) {
    float2 f; asm("mov.b64 {%0, %1}, %2;" : "=f"(f.x), "=f"(f.y) : "l"(v)); return f;
}

// 512 MB scratch, reused in place: pre0 -> ys0 -> pre1 -> ys1. Layout [t][b][h].
__device__ float g_buf[(size_t)TT * BB * HH];

#define ASTR 68    // As row stride: 16B-aligned, low conflict
#define BSTR 260   // Bs row stride: 16B-aligned pair loads

// h layout inside rec: index of global k in the half-interleaved buffer
// idx(k) = ((k & 127) >> 2) * 8 + (k >> 7) * 4 + (k & 3)
__device__ __forceinline__ int hidx(int k) {
    return ((k & 127) >> 2) * 8 + ((k >> 7) << 2) + (k & 3);
}

// ---------------------------------------------------------------------------
// K1: pre0[t,b,n] = x[b,t,:] . W_ih0[n,:] + b_ih0[n] + b_hh0[n]
// ---------------------------------------------------------------------------
__global__ void __launch_bounds__(256)
pre0_kernel(const float* __restrict__ x, const float* __restrict__ Wih,
            const float* __restrict__ bih, const float* __restrict__ bhh) {
    extern __shared__ float sm[];
    float* As = sm;                 // [64 k][ASTR]
    float* Bs = sm + 64 * ASTR;     // [64 k][BSTR]
    const int tid = threadIdx.x;
    const int m0 = blockIdx.x * 64;

    for (int e = tid; e < 64 * 64; e += 256) {
        int r = e >> 6, k = e & 63;
        int m = m0 + r;
        int b = m & (BB - 1);
        int t = m >> 8;
        As[k * ASTR + r] = x[((size_t)b * TT + t) * II + k];
    }
    for (int e = tid; e < 64 * 256; e += 256) {
        int n = e >> 6, k = e & 63;
        Bs[k * BSTR + n] = Wih[n * II + k];
    }
    __syncthreads();

    const int tm = tid & 7;
    const int tn = tid >> 3;
    ull acc2[8][4];
#pragma unroll
    for (int i = 0; i < 8; i++)
#pragma unroll
        for (int j = 0; j < 4; j++) acc2[i][j] = 0ull;

#pragma unroll 8
    for (int k = 0; k < 64; k++) {
        const float4* ar = (const float4*)&As[k * ASTR + tm * 8];
        float4 a0 = ar[0], a1 = ar[1];
        const ulonglong2* br = (const ulonglong2*)&Bs[k * BSTR + tn * 8];
        ulonglong2 q0 = br[0], q1 = br[1];
        ull b2[4] = {q0.x, q0.y, q1.x, q1.y};
        float a[8] = {a0.x, a0.y, a0.z, a0.w, a1.x, a1.y, a1.z, a1.w};
#pragma unroll
        for (int i = 0; i < 8; i++) {
            ull ad = pk2(a[i], a[i]);
#pragma unroll
            for (int j = 0; j < 4; j++) f2fma(acc2[i][j], ad, b2[j]);
        }
    }

#pragma unroll
    for (int j = 0; j < 4; j++) {
        int n0 = tn * 8 + 2 * j;
        float bias0 = bih[n0] + bhh[n0];
        float bias1 = bih[n0 + 1] + bhh[n0 + 1];
#pragma unroll
        for (int i = 0; i < 8; i++) {
            float2 v = up2(acc2[i][j]);
            size_t row = (size_t)(m0 + tm * 8 + i) * HH;
            g_buf[row + n0]     = v.x + bias0;
            g_buf[row + n0 + 1] = v.y + bias1;
        }
    }
}

// ---------------------------------------------------------------------------
// K3: in-place pre1: buf[m,n] = buf[m,:] . W_ih1[n,:] + b_ih1[n] + b_hh1[n]
// ---------------------------------------------------------------------------
__global__ void __launch_bounds__(256, 2)
pre1_kernel(const float* __restrict__ Wih, const float* __restrict__ bih,
            const float* __restrict__ bhh) {
    extern __shared__ float sm[];
    float* As = sm;                    // [256 k][ASTR]
    float* Bs = sm + 256 * ASTR;       // [32 k][BSTR]
    const int tid = threadIdx.x;
    const int m0 = blockIdx.x * 64;

    for (int e = tid; e < 64 * 256; e += 256) {
        int r = e >> 8, k = e & 255;
        As[k * ASTR + r] = g_buf[(size_t)(m0 + r) * HH + k];
    }

    const int tm = tid & 7;
    const int tn = tid >> 3;
    ull acc2[8][4];
#pragma unroll
    for (int i = 0; i < 8; i++)
#pragma unroll
        for (int j = 0; j < 4; j++) acc2[i][j] = 0ull;

    for (int kc = 0; kc < 8; kc++) {
        const int k0 = kc * 32;
        __syncthreads();
        for (int e = tid; e < 32 * 256; e += 256) {
            int n = e >> 5, kk = e & 31;
            Bs[kk * BSTR + n] = Wih[n * HH + k0 + kk];
        }
        __syncthreads();
#pragma unroll 8
        for (int kk = 0; kk < 32; kk++) {
            const float4* ar = (const float4*)&As[(k0 + kk) * ASTR + tm * 8];
            float4 a0 = ar[0], a1 = ar[1];
            const ulonglong2* br = (const ulonglong2*)&Bs[kk * BSTR + tn * 8];
            ulonglong2 q0 = br[0], q1 = br[1];
            ull b2[4] = {q0.x, q0.y, q1.x, q1.y};
            float a[8] = {a0.x, a0.y, a0.z, a0.w, a1.x, a1.y, a1.z, a1.w};
#pragma unroll
            for (int i = 0; i < 8; i++) {
                ull ad = pk2(a[i], a[i]);
#pragma unroll
                for (int j = 0; j < 4; j++) f2fma(acc2[i][j], ad, b2[j]);
            }
        }
    }

#pragma unroll
    for (int j = 0; j < 4; j++) {
        int n0 = tn * 8 + 2 * j;
        float bias0 = bih[n0] + bhh[n0];
        float bias1 = bih[n0 + 1] + bhh[n0 + 1];
#pragma unroll
        for (int i = 0; i < 8; i++) {
            float2 v = up2(acc2[i][j]);
            size_t row = (size_t)(m0 + tm * 8 + i) * HH;
            g_buf[row + n0]     = v.x + bias0;
            g_buf[row + n0 + 1] = v.y + bias1;
        }
    }
}

// ---------------------------------------------------------------------------
// K2: recurrence v6 — v4 budgets (64/64 W split, no spills) + v5 sync
// structure (lane-interleaved halves, shfl combine, ONE sync/step).
// Thread tid -> (n = tid>>1, half = tid&1); half's k-range = [half*128, +128):
//   - k_local  0..63  from 32 ull register pairs (64 regs)
//   - k_local 64..127 from a 128 KB smem tile (16 LDS.128/step, per-lane)
// h is stored HALF-INTERLEAVED: idx(k) = ((k&127)>>2)*8 + (k>>7)*4 + (k&3),
// so even/odd lanes' h loads are adjacent 16B (one 32B span = 1 wavefront,
// fixing v5's same-bank 512B split). Cross-half combine = one shfl_xor;
// even lane finalizes tanh + stores. No psum, single __syncthreads.
// ---------------------------------------------------------------------------
__global__ void __launch_bounds__(512, 1)
rec_kernel(const float* __restrict__ Whh, const float* __restrict__ h0,
           float* __restrict__ hT) {
    extern __shared__ float smd[];
    // Wsm: ulonglong2[16][512] = 128 KB | hbuf [2][NB][256] = 4 KB
    ulonglong2* Wsm = (ulonglong2*)smd;
    float* hbuf = smd + 16 * 512 * 4;

    const int tid = threadIdx.x;
    const int n = tid >> 1;
    const int half = tid & 1;
    const int b0 = blockIdx.x * NB;
    const int kb = half * 128;

    // Register W: k_local 0..63 as 32 ull pairs (pair j = floats 2j, 2j+1).
    ull W2[32];
    const ulonglong2* wp = (const ulonglong2*)(Whh + (size_t)n * HH + kb);
#pragma unroll
    for (int q = 0; q < 16; q++) {
        ulonglong2 v = wp[q];
        W2[2 * q]     = v.x;
        W2[2 * q + 1] = v.y;
    }
    // Smem W: k_local 64..127 (16 x ulonglong2 per thread, per-lane distinct).
#pragma unroll
    for (int j = 0; j < 16; j++)
        Wsm[j * 512 + tid] = wp[16 + j];

    // h init into buffer 0 (half-interleaved layout).
    {
        int b = tid >> 8, k = tid & 255;
        hbuf[b * 256 + hidx(k)] = h0[(b0 + b) * HH + k];
    }
    __syncthreads();

    for (int t = 0; t < TT; t++) {
        const int p = t & 1;
        const float* cur = hbuf + p * NB * 256;
        float* nxt = hbuf + (p ^ 1) * NB * 256;

        // even lanes prefetch pre-activations (LDG hides under FMA block)
        float pr[NB];
        if (half == 0) {
#pragma unroll
            for (int b = 0; b < NB; b++)
                pr[b] = g_buf[((size_t)t * BB + b0 + b) * HH + n];
        }

        // interleaved-h addressing: k_local chunk q lives at q*8 + half*4
        ull accR[NB], accS[NB];
#pragma unroll
        for (int b = 0; b < NB; b++) { accR[b] = 0ull; accS[b] = 0ull; }

        // register part: k_local 0..63 (chunks q = 0..15)
#pragma unroll
        for (int q = 0; q < 16; q++) {
#pragma unroll
            for (int b = 0; b < NB; b++) {
                ulonglong2 hv =
                    *(const ulonglong2*)&cur[b * 256 + q * 8 + half * 4];
                f2fma(accR[b], hv.x, W2[2 * q]);
                f2fma(accR[b], hv.y, W2[2 * q + 1]);
            }
        }
        // smem part: k_local 64..127 (chunks q = 16..31)
#pragma unroll
        for (int j = 0; j < 16; j++) {
            ulonglong2 w = Wsm[j * 512 + tid];
#pragma unroll
            for (int b = 0; b < NB; b++) {
                ulonglong2 hv =
                    *(const ulonglong2*)&cur[b * 256 + (16 + j) * 8 + half * 4];
                f2fma(accS[b], hv.x, w.x);
                f2fma(accS[b], hv.y, w.y);
            }
        }

        // combine: horizontal add + cross-half shfl (adjacent lane), finalize
#pragma unroll
        for (int b = 0; b < NB; b++) {
            float2 vr = up2(accR[b]);
            float2 vs = up2(accS[b]);
            float s = (vr.x + vr.y) + (vs.x + vs.y);
            float o = __shfl_xor_sync(0xFFFFFFFFu, s, 1);
            if (half == 0) {
                float hv = tanhf(pr[b] + s + o);
                nxt[b * 256 + hidx(n)] = hv;
                g_buf[((size_t)t * BB + b0 + b) * HH + n] = hv;
            }
        }
        __syncthreads();   // nxt visible to all before it becomes cur
    }

    // TT even -> final state in buffer 0
    if (half == 0) {
#pragma unroll
        for (int b = 0; b < NB; b++)
            hT[(b0 + b) * HH + n] = hbuf[b * 256 + hidx(n)];
    }
}

// ---------------------------------------------------------------------------
// K4: fc over the last F timesteps:
// out[b,f,o] = ys1[T-F+f, b, :] . fc_W[o,:] + fc_b[o]
// ---------------------------------------------------------------------------
__global__ void __launch_bounds__(256)
fc_kernel(const float* __restrict__ Wfc, const float* __restrict__ bfc,
          float* __restrict__ out) {
    __shared__ __align__(16) float xs[FF][HH];
    const int b = blockIdx.x;
    const int tid = threadIdx.x;
    for (int idx = tid; idx < FF * HH; idx += 256) {
        int f = idx >> 8, h = idx & 255;
        int t = TT - FF + f;
        xs[f][h] = g_buf[((size_t)t * BB + b) * HH + h];
    }
    __syncthreads();
    for (int fo = tid; fo < FF * OO; fo += 256) {
        int f = fo >> 6, o = fo & 63;
        float s = 0.f;
        const float4* wr = (const float4*)(Wfc + (size_t)o * HH);
        const float4* xr = (const float4*)&xs[f][0];
#pragma unroll
        for (int q = 0; q < 64; q++) {
            float4 w = wr[q], xv = xr[q];
            s += w.x * xv.x + w.y * xv.y + w.z * xv.z + w.w * xv.w;
        }
        out[((size_t)b * FF + f) * OO + o] = s + bfc[o];
    }
}

// ---------------------------------------------------------------------------
extern "C" void kernel_launch(void* const* d_in, const int* in_sizes, int n_in,
                              void* d_out, int out_size) {
    const float* x      = (const float*)d_in[0];
    const float* hidden = (const float*)d_in[1];
    const float* W_ih0  = (const float*)d_in[2];
    const float* W_hh0  = (const float*)d_in[3];
    const float* b_ih0  = (const float*)d_in[4];
    const float* b_hh0  = (const float*)d_in[5];
    const float* W_ih1  = (const float*)d_in[6];
    const float* W_hh1  = (const float*)d_in[7];
    const float* b_ih1  = (const float*)d_in[8];
    const float* b_hh1  = (const float*)d_in[9];
    const float* fc_W   = (const float*)d_in[10];
    const float* fc_b   = (const float*)d_in[11];

    float* out = (float*)d_out;                 // [B, F, O]
    float* hT  = out + (size_t)BB * FF * OO;    // [2, B, H]

    const int sm1 = (64 * ASTR + 64 * BSTR) * 4;            // ~84 KB
    const int sm3 = (256 * ASTR + 32 * BSTR) * 4;           // ~101 KB (occ 2)
    const int smr = 16 * 512 * 16 + 2 * NB * 256 * 4;       // 128 KB + 4 KB
    cudaFuncSetAttribute(pre0_kernel, cudaFuncAttributeMaxDynamicSharedMemorySize, sm1);
    cudaFuncSetAttribute(pre1_kernel, cudaFuncAttributeMaxDynamicSharedMemorySize, sm3);
    cudaFuncSetAttribute(rec_kernel,  cudaFuncAttributeMaxDynamicSharedMemorySize, smr);

    const int mblocks = TT * BB / 64;   // 8192
    const int rblocks = BB / NB;        // 128 CTAs, 512 threads each

    pre0_kernel<<<mblocks, 256, sm1>>>(x, W_ih0, b_ih0, b_hh0);
    rec_kernel<<<rblocks, 512, smr>>>(W_hh0, hidden, hT);
    pre1_kernel<<<mblocks, 256, sm3>>>(W_ih1, b_ih1, b_hh1);
    rec_kernel<<<rblocks, 512, smr>>>(W_hh1, hidden + (size_t)BB * HH,
                                      hT + (size_t)BB * HH);
    fc_kernel<<<BB, 256>>>(fc_W, fc_b, out);
}